// round 16
// baseline (speedup 1.0000x reference)
#include <cuda_runtime.h>
#include <cuda_fp16.h>
#include <cstdint>

#define N_NODES 50000
#define N_EDGES 625000
#define D 128
#define NBLK 196                     // scan blocks (50000/256)
#define EBLK 2442                    // edge blocks (625000/256)
#define M_BLK 128
#define OUT_BLOCKS 391               // ceil(50000/128) gemm blocks total
#define G1 196                       // gemm blocks co-launched with scan
#define G2 (OUT_BLOCKS - G1)         // 195, co-launched with fill
#define SCAN_READY 0x40000000

// ---------------------------------------------------------------------------
// Device scratch. g_cnt invariant: starts 0 (module load), hist adds, fill
// subtracts back to exactly 0 -> no zeroing needed, deterministic per replay.
// ---------------------------------------------------------------------------
__device__ int    g_cnt[N_NODES];
__device__ int    g_state[NBLK];         // lookback scan: aggregate | READY
__device__ int    g_off[N_NODES + 1];    // CSR row offsets
__device__ int    g_sadj[N_EDGES];       // CSR: src node per in-edge slot
__device__ __half g_y[N_NODES * D];      // y = x @ Wn, fp16 (gathered by agg)
__device__ __half g_Wh[256 * D];         // B^T [n][k]: n<128 Ws^T, n>=128 Wn^T

// ---------------------------------------------------------------------------
// 1) fused init: blocks [0,EBLK) histogram dst; blocks [EBLK,EBLK+128):
//    W -> [n][k] fp16 transpose (+ g_state clear)
// ---------------------------------------------------------------------------
__global__ void __launch_bounds__(256) init_hist_kernel(
    const int* __restrict__ dst,
    const float* __restrict__ Ws, const float* __restrict__ Wn)
{
    int bid = blockIdx.x, t = threadIdx.x;
    if (bid < EBLK) {
        int e = bid * 256 + t;
        if (e < N_EDGES) atomicAdd(&g_cnt[dst[e]], 1);
    } else {
        int wb = bid - EBLK;                 // 0..127
        if (wb == 0 && t < NBLK) g_state[t] = 0;
        int n = wb * 2 + (t >> 7);           // 0..255 (output col: Ws then Wn)
        int k = t & 127;                     // 0..127 (input dim)
        float w = (n < D) ? Ws[k * D + n] : Wn[k * D + (n - D)];
        g_Wh[n * D + k] = __float2half_rn(w);
    }
}

// ---------------------------------------------------------------------------
// GEMM block body (R13 config — measured best): A = x fp16 (128 rows/block),
// B^T = [Ws|Wn] fp16 (N=256), 8 warps x 16 rows, N-chunked 4x64.
// Chunks 0-1 -> out = x@Ws + b (fp32); chunks 2-3 -> g_y = fp16(x@Wn).
// ---------------------------------------------------------------------------
#define GEMM_THREADS 256
#define A_STRIDE 136
#define B_STRIDE 136
#define SM_A    0
#define SM_B    (M_BLK * A_STRIDE)                      // 17408 halves
#define SMEM_HALVES (M_BLK * A_STRIDE + 64 * B_STRIDE)  // 26112
#define SMEM_BYTES  (SMEM_HALVES * 2)                   // 52224

__device__ __forceinline__ void ldsm_x4(uint32_t* r, uint32_t addr) {
    asm volatile("ldmatrix.sync.aligned.m8n8.x4.shared.b16 {%0,%1,%2,%3}, [%4];"
                 : "=r"(r[0]), "=r"(r[1]), "=r"(r[2]), "=r"(r[3]) : "r"(addr));
}
__device__ __forceinline__ void mma16816(float* c, const uint32_t* a, const uint32_t* b) {
    asm volatile(
        "mma.sync.aligned.m16n8k16.row.col.f32.f16.f16.f32 "
        "{%0,%1,%2,%3}, {%4,%5,%6,%7}, {%8,%9}, {%0,%1,%2,%3};"
        : "+f"(c[0]), "+f"(c[1]), "+f"(c[2]), "+f"(c[3])
        : "r"(a[0]), "r"(a[1]), "r"(a[2]), "r"(a[3]), "r"(b[0]), "r"(b[1]));
}

__device__ __forceinline__ void gemm_block(
    int gb,                      // gemm block index 0..OUT_BLOCKS-1
    const float* __restrict__ x,
    const float* __restrict__ bias,
    float*       __restrict__ out,
    __half* sm)
{
    __half* A_h = sm + SM_A;
    __half* B_h = sm + SM_B;

    const int t    = threadIdx.x;
    const int warp = t >> 5;           // 0..7, warp owns rows [16*warp, +16)
    const int lane = t & 31;
    const int base = gb * M_BLK;

    // ---- stage A once: 128 rows of x, fp32 -> fp16 ----
    {
        int row_off = t >> 5;          // 0..7
        int l16     = t & 31;          // float4 index (k = 4*l16)
        #pragma unroll 4
        for (int it = 0; it < 16; it++) {
            int row  = it * 8 + row_off;
            int node = base + row;
            float4 v = make_float4(0.f, 0.f, 0.f, 0.f);
            if (node < N_NODES)
                v = reinterpret_cast<const float4*>(x + (size_t)node * D)[l16];
            __half2 p0 = __floats2half2_rn(v.x, v.y);
            __half2 p1 = __floats2half2_rn(v.z, v.w);
            uint2 u;
            u.x = *reinterpret_cast<uint32_t*>(&p0);
            u.y = *reinterpret_cast<uint32_t*>(&p1);
            *reinterpret_cast<uint2*>(A_h + row * A_STRIDE + l16 * 4) = u;
        }
    }

    const int mrow = warp * 16;
    const int a_r  = lane & 15;
    const int a_k  = (lane >> 4) * 8;
    const int b_m  = lane >> 3;        // x4 matrix idx 0..3
    const int b_r  = lane & 7;
    const int b_no = (b_m >> 1) * 8;   // n offset 0/8
    const int b_ko = (b_m & 1) * 8;    // k offset 0/8

    for (int nc = 0; nc < 4; nc++) {
        __syncthreads();
        {
            #pragma unroll 2
            for (int idx = t; idx < 64 * 16; idx += GEMM_THREADS) {
                int n = idx >> 4, q = idx & 15;       // q: uint4 (8 halves)
                int ng = nc * 64 + n;
                const uint4* sh = reinterpret_cast<const uint4*>(g_Wh + ng * D) + q;
                *reinterpret_cast<uint4*>(B_h + n * B_STRIDE + q * 8) = *sh;
            }
        }
        __syncthreads();

        float c[8][4];
        #pragma unroll
        for (int nt = 0; nt < 8; nt++)
            #pragma unroll
            for (int i = 0; i < 4; i++) c[nt][i] = 0.f;

        #pragma unroll
        for (int kt = 0; kt < 8; kt++) {
            int kk = kt * 16;

            uint32_t a4[4];
            ldsm_x4(a4, (uint32_t)__cvta_generic_to_shared(
                A_h + (mrow + a_r) * A_STRIDE + kk + a_k));

            #pragma unroll
            for (int np = 0; np < 4; np++) {          // n-tile pairs (16 cols)
                uint32_t b4[4];
                int nrow = np * 16 + b_no + b_r;
                ldsm_x4(b4, (uint32_t)__cvta_generic_to_shared(
                    B_h + nrow * B_STRIDE + kk + b_ko));
                mma16816(c[np * 2 + 0], a4, b4 + 0);
                mma16816(c[np * 2 + 1], a4, b4 + 2);
            }
        }

        // ---- epilogue: chunks 0-1 -> out (+bias); chunks 2-3 -> g_y fp16 ----
        #pragma unroll
        for (int nt = 0; nt < 8; nt++) {
            int ng = nc * 64 + nt * 8 + (lane & 3) * 2;   // global output col
            int r0 = base + mrow + (lane >> 2);
            int r1 = r0 + 8;
            if (nc < 2) {
                float2 bv = *reinterpret_cast<const float2*>(bias + ng);
                if (r0 < N_NODES) {
                    float2 o; o.x = c[nt][0] + bv.x; o.y = c[nt][1] + bv.y;
                    *reinterpret_cast<float2*>(out + (size_t)r0 * D + ng) = o;
                }
                if (r1 < N_NODES) {
                    float2 o; o.x = c[nt][2] + bv.x; o.y = c[nt][3] + bv.y;
                    *reinterpret_cast<float2*>(out + (size_t)r1 * D + ng) = o;
                }
            } else {
                int col = ng - 128;
                if (r0 < N_NODES) {
                    __half2 h = __floats2half2_rn(c[nt][0], c[nt][1]);
                    *reinterpret_cast<__half2*>(g_y + (size_t)r0 * D + col) = h;
                }
                if (r1 < N_NODES) {
                    __half2 h = __floats2half2_rn(c[nt][2], c[nt][3]);
                    *reinterpret_cast<__half2*>(g_y + (size_t)r1 * D + col) = h;
                }
            }
        }
    }
}

// ---------------------------------------------------------------------------
// 2) LAUNCH 2: gemm blocks [0,G1) || decoupled-lookback scan.
// ---------------------------------------------------------------------------
__global__ void __launch_bounds__(GEMM_THREADS) scan_gemm_kernel(
    const float* __restrict__ x,
    const float* __restrict__ bias,
    float*       __restrict__ out)
{
    extern __shared__ __half smx[];
    if (blockIdx.x < G1) {
        gemm_block(blockIdx.x, x, bias, out, smx);
        return;
    }

    __shared__ int s[256];
    __shared__ int red[256];
    int t = threadIdx.x, bid = blockIdx.x - G1;
    int i = bid * 256 + t;

    int v = (i < N_NODES) ? g_cnt[i] : 0;
    s[t] = v; __syncthreads();
    #pragma unroll
    for (int d = 1; d < 256; d <<= 1) {
        int add = (t >= d) ? s[t - d] : 0;
        __syncthreads();
        s[t] += add; __syncthreads();
    }
    if (t == 0) atomicExch(&g_state[bid], s[255] | SCAN_READY);

    int pref = 0;
    if (t < bid) {
        int st;
        do { st = atomicAdd(&g_state[t], 0); } while (!(st & SCAN_READY));
        pref = st & (SCAN_READY - 1);
    }
    red[t] = pref; __syncthreads();
    #pragma unroll
    for (int sft = 128; sft > 0; sft >>= 1) {
        if (t < sft) red[t] += red[t + sft];
        __syncthreads();
    }
    int prefix = red[0];

    if (i < N_NODES) g_off[i] = (s[t] - v) + prefix;
    if (i == 0)      g_off[N_NODES] = N_EDGES;
}

// ---------------------------------------------------------------------------
// 3) LAUNCH 3: gemm blocks [0,G2) (rows from G1*128) || CSR fill.
// ---------------------------------------------------------------------------
__global__ void __launch_bounds__(GEMM_THREADS) fill_gemm_kernel(
    const float* __restrict__ x,
    const float* __restrict__ bias,
    float*       __restrict__ out,
    const int* __restrict__ src,
    const int* __restrict__ dst)
{
    extern __shared__ __half smx[];
    if (blockIdx.x < G2) {
        gemm_block(G1 + blockIdx.x, x, bias, out, smx);
        return;
    }

    int e = (blockIdx.x - G2) * 256 + threadIdx.x;
    if (e >= N_EDGES) return;
    int d = __ldg(&dst[e]);
    int p = atomicSub(&g_cnt[d], 1) - 1;
    g_sadj[g_off[d] + p] = __ldg(&src[e]);
}

// ---------------------------------------------------------------------------
// 4) aggregate y over in-edges, RMW-add the mean into out.
//    One warp per node. Lane-parallel sadj prefetch (1 coalesced LDG per
//    32 edges) + shfl broadcast + 4-way independent gathers (MLP 4) —
//    replaces the chained sadj->gather per-iteration dependency.
// ---------------------------------------------------------------------------
__global__ void __launch_bounds__(256) agg_kernel(float* __restrict__ out) {
    int v    = (blockIdx.x * blockDim.x + threadIdx.x) >> 5;
    int lane = threadIdx.x & 31;
    if (v >= N_NODES) return;

    int beg = g_off[v];
    int end = g_off[v + 1];

    float4 acc = make_float4(0.f, 0.f, 0.f, 0.f);

    for (int chunk = beg; chunk < end; chunk += 32) {
        int n_in = min(32, end - chunk);
        int sv = (chunk + lane < end) ? g_sadj[chunk + lane] : 0;

        int j = 0;
        for (; j + 4 <= n_in; j += 4) {
            int s0 = __shfl_sync(0xffffffffu, sv, j + 0);
            int s1 = __shfl_sync(0xffffffffu, sv, j + 1);
            int s2 = __shfl_sync(0xffffffffu, sv, j + 2);
            int s3 = __shfl_sync(0xffffffffu, sv, j + 3);
            uint2 p0 = reinterpret_cast<const uint2*>(g_y + (size_t)s0 * D)[lane];
            uint2 p1 = reinterpret_cast<const uint2*>(g_y + (size_t)s1 * D)[lane];
            uint2 p2 = reinterpret_cast<const uint2*>(g_y + (size_t)s2 * D)[lane];
            uint2 p3 = reinterpret_cast<const uint2*>(g_y + (size_t)s3 * D)[lane];
            float2 a0 = __half22float2(*reinterpret_cast<const __half2*>(&p0.x));
            float2 b0 = __half22float2(*reinterpret_cast<const __half2*>(&p0.y));
            float2 a1 = __half22float2(*reinterpret_cast<const __half2*>(&p1.x));
            float2 b1 = __half22float2(*reinterpret_cast<const __half2*>(&p1.y));
            float2 a2 = __half22float2(*reinterpret_cast<const __half2*>(&p2.x));
            float2 b2 = __half22float2(*reinterpret_cast<const __half2*>(&p2.y));
            float2 a3 = __half22float2(*reinterpret_cast<const __half2*>(&p3.x));
            float2 b3 = __half22float2(*reinterpret_cast<const __half2*>(&p3.y));
            acc.x += (a0.x + a1.x) + (a2.x + a3.x);
            acc.y += (a0.y + a1.y) + (a2.y + a3.y);
            acc.z += (b0.x + b1.x) + (b2.x + b3.x);
            acc.w += (b0.y + b1.y) + (b2.y + b3.y);
        }
        for (; j < n_in; j++) {
            int s0 = __shfl_sync(0xffffffffu, sv, j);
            uint2 p0 = reinterpret_cast<const uint2*>(g_y + (size_t)s0 * D)[lane];
            float2 a0 = __half22float2(*reinterpret_cast<const __half2*>(&p0.x));
            float2 b0 = __half22float2(*reinterpret_cast<const __half2*>(&p0.y));
            acc.x += a0.x; acc.y += a0.y; acc.z += b0.x; acc.w += b0.y;
        }
    }

    int deg = end - beg;
    float inv = (deg > 0) ? (1.0f / (float)deg) : 0.0f;
    float4* op = reinterpret_cast<float4*>(out + (size_t)v * D + lane * 4);
    float4 cur = *op;
    cur.x += acc.x * inv; cur.y += acc.y * inv;
    cur.z += acc.z * inv; cur.w += acc.w * inv;
    *op = cur;
}

// ---------------------------------------------------------------------------
// Launch (4 kernels, single stream):
//   1. hist + Wconv          2. scan || gemm[0:196)
//   3. fill || gemm[196:391) 4. agg
// Inputs: x, src, dst, W_self, W_neigh, b
// ---------------------------------------------------------------------------
extern "C" void kernel_launch(void* const* d_in, const int* in_sizes, int n_in,
                              void* d_out, int out_size)
{
    const float* x   = (const float*)d_in[0];
    const int*   src = (const int*)  d_in[1];
    const int*   dst = (const int*)  d_in[2];
    const float* Ws  = (const float*)d_in[3];
    const float* Wn  = (const float*)d_in[4];
    const float* b   = (const float*)d_in[5];
    float*       out = (float*)d_out;

    static bool attr_set = false;
    if (!attr_set) {
        cudaFuncSetAttribute(scan_gemm_kernel,
                             cudaFuncAttributeMaxDynamicSharedMemorySize, SMEM_BYTES);
        cudaFuncSetAttribute(fill_gemm_kernel,
                             cudaFuncAttributeMaxDynamicSharedMemorySize, SMEM_BYTES);
        attr_set = true;
    }

    init_hist_kernel<<<EBLK + 128, 256>>>(dst, Ws, Wn);
    scan_gemm_kernel<<<G1 + NBLK, GEMM_THREADS, SMEM_BYTES>>>(x, b, out);
    fill_gemm_kernel<<<G2 + EBLK, GEMM_THREADS, SMEM_BYTES>>>(x, b, out, src, dst);
    agg_kernel<<<(N_NODES * 32 + 255) / 256, 256>>>(out);
}

// round 17
// speedup vs baseline: 1.0502x; 1.0502x over previous
#include <cuda_runtime.h>
#include <cuda_fp16.h>
#include <cstdint>

#define N_NODES 50000
#define N_EDGES 625000
#define D 128
#define NBLK 196                     // scan blocks (50000/256)
#define EBLK 2442                    // edge blocks (625000/256)
#define M_BLK 128
#define OUT_BLOCKS 391               // ceil(50000/128) gemm blocks total
#define G1 196                       // gemm blocks co-launched with scan
#define G2 (OUT_BLOCKS - G1)         // 195, co-launched with fill
#define SCAN_READY 0x40000000

// ---------------------------------------------------------------------------
// Device scratch. g_cnt invariant: starts 0 (module load), hist adds, fill
// subtracts back to exactly 0 -> no zeroing needed, deterministic per replay.
// ---------------------------------------------------------------------------
__device__ int    g_cnt[N_NODES];
__device__ int    g_state[NBLK];         // lookback scan: aggregate | READY
__device__ int    g_off[N_NODES + 1];    // CSR row offsets
__device__ int    g_sadj[N_EDGES];       // CSR: src node per in-edge slot
__device__ __half g_y[N_NODES * D];      // y = x @ Wn, fp16 (gathered by agg)
__device__ __half g_Wh[256 * D];         // B^T [n][k]: n<128 Ws^T, n>=128 Wn^T

// ---------------------------------------------------------------------------
// 1) fused init: blocks [0,EBLK) histogram dst; blocks [EBLK,EBLK+128):
//    W -> [n][k] fp16 transpose (+ g_state clear)
// ---------------------------------------------------------------------------
__global__ void __launch_bounds__(256) init_hist_kernel(
    const int* __restrict__ dst,
    const float* __restrict__ Ws, const float* __restrict__ Wn)
{
    int bid = blockIdx.x, t = threadIdx.x;
    if (bid < EBLK) {
        int e = bid * 256 + t;
        if (e < N_EDGES) atomicAdd(&g_cnt[dst[e]], 1);
    } else {
        int wb = bid - EBLK;                 // 0..127
        if (wb == 0 && t < NBLK) g_state[t] = 0;
        int n = wb * 2 + (t >> 7);           // 0..255 (output col: Ws then Wn)
        int k = t & 127;                     // 0..127 (input dim)
        float w = (n < D) ? Ws[k * D + n] : Wn[k * D + (n - D)];
        g_Wh[n * D + k] = __float2half_rn(w);
    }
}

// ---------------------------------------------------------------------------
// GEMM block body (R13 config — measured best): A = x fp16 (128 rows/block),
// B^T = [Ws|Wn] fp16 (N=256), 8 warps x 16 rows, N-chunked 4x64.
// Chunks 0-1 -> out = x@Ws + b (fp32); chunks 2-3 -> g_y = fp16(x@Wn).
// ---------------------------------------------------------------------------
#define GEMM_THREADS 256
#define A_STRIDE 136
#define B_STRIDE 136
#define SM_A    0
#define SM_B    (M_BLK * A_STRIDE)                      // 17408 halves
#define SMEM_HALVES (M_BLK * A_STRIDE + 64 * B_STRIDE)  // 26112
#define SMEM_BYTES  (SMEM_HALVES * 2)                   // 52224

__device__ __forceinline__ void ldsm_x4(uint32_t* r, uint32_t addr) {
    asm volatile("ldmatrix.sync.aligned.m8n8.x4.shared.b16 {%0,%1,%2,%3}, [%4];"
                 : "=r"(r[0]), "=r"(r[1]), "=r"(r[2]), "=r"(r[3]) : "r"(addr));
}
__device__ __forceinline__ void mma16816(float* c, const uint32_t* a, const uint32_t* b) {
    asm volatile(
        "mma.sync.aligned.m16n8k16.row.col.f32.f16.f16.f32 "
        "{%0,%1,%2,%3}, {%4,%5,%6,%7}, {%8,%9}, {%0,%1,%2,%3};"
        : "+f"(c[0]), "+f"(c[1]), "+f"(c[2]), "+f"(c[3])
        : "r"(a[0]), "r"(a[1]), "r"(a[2]), "r"(a[3]), "r"(b[0]), "r"(b[1]));
}

__device__ __forceinline__ void gemm_block(
    int gb,                      // gemm block index 0..OUT_BLOCKS-1
    const float* __restrict__ x,
    const float* __restrict__ bias,
    float*       __restrict__ out,
    __half* sm)
{
    __half* A_h = sm + SM_A;
    __half* B_h = sm + SM_B;

    const int t    = threadIdx.x;
    const int warp = t >> 5;           // 0..7, warp owns rows [16*warp, +16)
    const int lane = t & 31;
    const int base = gb * M_BLK;

    // ---- stage A once: 128 rows of x, fp32 -> fp16 ----
    {
        int row_off = t >> 5;          // 0..7
        int l16     = t & 31;          // float4 index (k = 4*l16)
        #pragma unroll 4
        for (int it = 0; it < 16; it++) {
            int row  = it * 8 + row_off;
            int node = base + row;
            float4 v = make_float4(0.f, 0.f, 0.f, 0.f);
            if (node < N_NODES)
                v = reinterpret_cast<const float4*>(x + (size_t)node * D)[l16];
            __half2 p0 = __floats2half2_rn(v.x, v.y);
            __half2 p1 = __floats2half2_rn(v.z, v.w);
            uint2 u;
            u.x = *reinterpret_cast<uint32_t*>(&p0);
            u.y = *reinterpret_cast<uint32_t*>(&p1);
            *reinterpret_cast<uint2*>(A_h + row * A_STRIDE + l16 * 4) = u;
        }
    }

    const int mrow = warp * 16;
    const int a_r  = lane & 15;
    const int a_k  = (lane >> 4) * 8;
    const int b_m  = lane >> 3;        // x4 matrix idx 0..3
    const int b_r  = lane & 7;
    const int b_no = (b_m >> 1) * 8;   // n offset 0/8
    const int b_ko = (b_m & 1) * 8;    // k offset 0/8

    for (int nc = 0; nc < 4; nc++) {
        __syncthreads();
        {
            #pragma unroll 2
            for (int idx = t; idx < 64 * 16; idx += GEMM_THREADS) {
                int n = idx >> 4, q = idx & 15;       // q: uint4 (8 halves)
                int ng = nc * 64 + n;
                const uint4* sh = reinterpret_cast<const uint4*>(g_Wh + ng * D) + q;
                *reinterpret_cast<uint4*>(B_h + n * B_STRIDE + q * 8) = *sh;
            }
        }
        __syncthreads();

        float c[8][4];
        #pragma unroll
        for (int nt = 0; nt < 8; nt++)
            #pragma unroll
            for (int i = 0; i < 4; i++) c[nt][i] = 0.f;

        #pragma unroll
        for (int kt = 0; kt < 8; kt++) {
            int kk = kt * 16;

            uint32_t a4[4];
            ldsm_x4(a4, (uint32_t)__cvta_generic_to_shared(
                A_h + (mrow + a_r) * A_STRIDE + kk + a_k));

            #pragma unroll
            for (int np = 0; np < 4; np++) {          // n-tile pairs (16 cols)
                uint32_t b4[4];
                int nrow = np * 16 + b_no + b_r;
                ldsm_x4(b4, (uint32_t)__cvta_generic_to_shared(
                    B_h + nrow * B_STRIDE + kk + b_ko));
                mma16816(c[np * 2 + 0], a4, b4 + 0);
                mma16816(c[np * 2 + 1], a4, b4 + 2);
            }
        }

        // ---- epilogue: chunks 0-1 -> out (+bias); chunks 2-3 -> g_y fp16 ----
        #pragma unroll
        for (int nt = 0; nt < 8; nt++) {
            int ng = nc * 64 + nt * 8 + (lane & 3) * 2;   // global output col
            int r0 = base + mrow + (lane >> 2);
            int r1 = r0 + 8;
            if (nc < 2) {
                float2 bv = *reinterpret_cast<const float2*>(bias + ng);
                if (r0 < N_NODES) {
                    float2 o; o.x = c[nt][0] + bv.x; o.y = c[nt][1] + bv.y;
                    *reinterpret_cast<float2*>(out + (size_t)r0 * D + ng) = o;
                }
                if (r1 < N_NODES) {
                    float2 o; o.x = c[nt][2] + bv.x; o.y = c[nt][3] + bv.y;
                    *reinterpret_cast<float2*>(out + (size_t)r1 * D + ng) = o;
                }
            } else {
                int col = ng - 128;
                if (r0 < N_NODES) {
                    __half2 h = __floats2half2_rn(c[nt][0], c[nt][1]);
                    *reinterpret_cast<__half2*>(g_y + (size_t)r0 * D + col) = h;
                }
                if (r1 < N_NODES) {
                    __half2 h = __floats2half2_rn(c[nt][2], c[nt][3]);
                    *reinterpret_cast<__half2*>(g_y + (size_t)r1 * D + col) = h;
                }
            }
        }
    }
}

// ---------------------------------------------------------------------------
// 2) LAUNCH 2: gemm blocks [0,G1) || decoupled-lookback scan.
// ---------------------------------------------------------------------------
__global__ void __launch_bounds__(GEMM_THREADS) scan_gemm_kernel(
    const float* __restrict__ x,
    const float* __restrict__ bias,
    float*       __restrict__ out)
{
    extern __shared__ __half smx[];
    if (blockIdx.x < G1) {
        gemm_block(blockIdx.x, x, bias, out, smx);
        return;
    }

    __shared__ int s[256];
    __shared__ int red[256];
    int t = threadIdx.x, bid = blockIdx.x - G1;
    int i = bid * 256 + t;

    int v = (i < N_NODES) ? g_cnt[i] : 0;
    s[t] = v; __syncthreads();
    #pragma unroll
    for (int d = 1; d < 256; d <<= 1) {
        int add = (t >= d) ? s[t - d] : 0;
        __syncthreads();
        s[t] += add; __syncthreads();
    }
    if (t == 0) atomicExch(&g_state[bid], s[255] | SCAN_READY);

    int pref = 0;
    if (t < bid) {
        int st;
        do { st = atomicAdd(&g_state[t], 0); } while (!(st & SCAN_READY));
        pref = st & (SCAN_READY - 1);
    }
    red[t] = pref; __syncthreads();
    #pragma unroll
    for (int sft = 128; sft > 0; sft >>= 1) {
        if (t < sft) red[t] += red[t + sft];
        __syncthreads();
    }
    int prefix = red[0];

    if (i < N_NODES) g_off[i] = (s[t] - v) + prefix;
    if (i == 0)      g_off[N_NODES] = N_EDGES;
}

// ---------------------------------------------------------------------------
// 3) LAUNCH 3: gemm blocks [0,G2) (rows from G1*128) || CSR fill.
// ---------------------------------------------------------------------------
__global__ void __launch_bounds__(GEMM_THREADS) fill_gemm_kernel(
    const float* __restrict__ x,
    const float* __restrict__ bias,
    float*       __restrict__ out,
    const int* __restrict__ src,
    const int* __restrict__ dst)
{
    extern __shared__ __half smx[];
    if (blockIdx.x < G2) {
        gemm_block(G1 + blockIdx.x, x, bias, out, smx);
        return;
    }

    int e = (blockIdx.x - G2) * 256 + threadIdx.x;
    if (e >= N_EDGES) return;
    int d = __ldg(&dst[e]);
    int p = atomicSub(&g_cnt[d], 1) - 1;
    g_sadj[g_off[d] + p] = __ldg(&src[e]);
}

// ---------------------------------------------------------------------------
// 4) aggregate y over in-edges, RMW-add the mean into out.
//    HALF-WARP per node: lanes [0,16) -> node 2w, lanes [16,32) -> node 2w+1.
//    Each lane loads uint4 (8 halves); 16 lanes = full 256B row. Two
//    independent node chains per warp x 2-way edge unroll = MLP 4.
// ---------------------------------------------------------------------------
__global__ void __launch_bounds__(256) agg_kernel(float* __restrict__ out) {
    int hw  = (blockIdx.x * blockDim.x + threadIdx.x) >> 4;  // half-warp id = node
    int sub = threadIdx.x & 15;                              // lane within half-warp
    if (hw >= N_NODES) return;
    int v = hw;

    int beg = g_off[v];
    int end = g_off[v + 1];

    float acc[8];
    #pragma unroll
    for (int j = 0; j < 8; j++) acc[j] = 0.f;

    int i = beg;
    for (; i + 1 < end; i += 2) {
        int s0 = g_sadj[i];
        int s1 = g_sadj[i + 1];
        uint4 p0 = reinterpret_cast<const uint4*>(g_y + (size_t)s0 * D)[sub];
        uint4 p1 = reinterpret_cast<const uint4*>(g_y + (size_t)s1 * D)[sub];
        const __half2* h0 = reinterpret_cast<const __half2*>(&p0);
        const __half2* h1 = reinterpret_cast<const __half2*>(&p1);
        #pragma unroll
        for (int j = 0; j < 4; j++) {
            float2 f0 = __half22float2(h0[j]);
            float2 f1 = __half22float2(h1[j]);
            acc[2*j]   += f0.x + f1.x;
            acc[2*j+1] += f0.y + f1.y;
        }
    }
    if (i < end) {
        int s0 = g_sadj[i];
        uint4 p0 = reinterpret_cast<const uint4*>(g_y + (size_t)s0 * D)[sub];
        const __half2* h0 = reinterpret_cast<const __half2*>(&p0);
        #pragma unroll
        for (int j = 0; j < 4; j++) {
            float2 f0 = __half22float2(h0[j]);
            acc[2*j]   += f0.x;
            acc[2*j+1] += f0.y;
        }
    }

    int deg = end - beg;
    float inv = (deg > 0) ? (1.0f / (float)deg) : 0.0f;
    float* op = out + (size_t)v * D + sub * 8;
    float4 c0 = *reinterpret_cast<float4*>(op);
    float4 c1 = *reinterpret_cast<float4*>(op + 4);
    c0.x += acc[0] * inv; c0.y += acc[1] * inv;
    c0.z += acc[2] * inv; c0.w += acc[3] * inv;
    c1.x += acc[4] * inv; c1.y += acc[5] * inv;
    c1.z += acc[6] * inv; c1.w += acc[7] * inv;
    *reinterpret_cast<float4*>(op)     = c0;
    *reinterpret_cast<float4*>(op + 4) = c1;
}

// ---------------------------------------------------------------------------
// Launch (4 kernels, single stream):
//   1. hist + Wconv          2. scan || gemm[0:196)
//   3. fill || gemm[196:391) 4. agg
// Inputs: x, src, dst, W_self, W_neigh, b
// ---------------------------------------------------------------------------
extern "C" void kernel_launch(void* const* d_in, const int* in_sizes, int n_in,
                              void* d_out, int out_size)
{
    const float* x   = (const float*)d_in[0];
    const int*   src = (const int*)  d_in[1];
    const int*   dst = (const int*)  d_in[2];
    const float* Ws  = (const float*)d_in[3];
    const float* Wn  = (const float*)d_in[4];
    const float* b   = (const float*)d_in[5];
    float*       out = (float*)d_out;

    static bool attr_set = false;
    if (!attr_set) {
        cudaFuncSetAttribute(scan_gemm_kernel,
                             cudaFuncAttributeMaxDynamicSharedMemorySize, SMEM_BYTES);
        cudaFuncSetAttribute(fill_gemm_kernel,
                             cudaFuncAttributeMaxDynamicSharedMemorySize, SMEM_BYTES);
        attr_set = true;
    }

    init_hist_kernel<<<EBLK + 128, 256>>>(dst, Ws, Wn);
    scan_gemm_kernel<<<G1 + NBLK, GEMM_THREADS, SMEM_BYTES>>>(x, b, out);
    fill_gemm_kernel<<<G2 + EBLK, GEMM_THREADS, SMEM_BYTES>>>(x, b, out, src, dst);
    // half-warp per node: 50000 * 16 threads
    agg_kernel<<<(N_NODES * 16 + 255) / 256, 256>>>(out);
}